// round 1
// baseline (speedup 1.0000x reference)
#include <cuda_runtime.h>
#include <cuda_bf16.h>
#include <cstdint>

// out[n,o] = sum_i x[n,i] * sign(W[o,i]) + b[o]
// N = IN = OUT = 4096, fp32 in/out.
//
// Strategy: sign(W) is exact in bf16. Split x = x_hi + x_lo (both bf16) so the
// bf16 MMA pair reproduces fp32 x to ~2^-17 relative. Two fused bf16 GEMMs with
// fp32 accumulation, mma.sync m16n8k16, cp.async double-buffered smem tiles.

#define N_DIM 4096
constexpr int MTILE = 128;
constexpr int NTILE = 128;
constexpr int KTILE = 32;
constexpr int NKT = N_DIM / KTILE;          // 128 k-iterations
constexpr int S_STRIDE = 40;                // padded bf16 row stride (80B): bank-conflict-free ldmatrix
constexpr int TILE_ELEMS = 128 * S_STRIDE;  // 5120 bf16 per tile
constexpr int STAGE_ELEMS = 3 * TILE_ELEMS; // A_hi, A_lo, B
constexpr int SMEM_BYTES = 2 * STAGE_ELEMS * (int)sizeof(__nv_bfloat16); // 61440

// Scratch (allocation-free rule: __device__ globals)
__device__ __nv_bfloat16 g_xhi[(size_t)N_DIM * N_DIM];
__device__ __nv_bfloat16 g_xlo[(size_t)N_DIM * N_DIM];
__device__ __nv_bfloat16 g_wb [(size_t)N_DIM * N_DIM];

// ---------------------------------------------------------------------------
// Prep: binarize W, split x into hi/lo bf16. Vectorized float4.
// ---------------------------------------------------------------------------
__global__ void prep_kernel(const float4* __restrict__ x,
                            const float4* __restrict__ W, int n4) {
    int i = blockIdx.x * blockDim.x + threadIdx.x;
    if (i >= n4) return;
    float4 xv = x[i];
    float4 wv = W[i];
    float xs[4] = {xv.x, xv.y, xv.z, xv.w};
    float ws[4] = {wv.x, wv.y, wv.z, wv.w};

    alignas(8) __nv_bfloat16 hi[4];
    alignas(8) __nv_bfloat16 lo[4];
    alignas(8) __nv_bfloat16 wb[4];
#pragma unroll
    for (int j = 0; j < 4; j++) {
        __nv_bfloat16 h = __float2bfloat16(xs[j]);
        hi[j] = h;
        lo[j] = __float2bfloat16(xs[j] - __bfloat162float(h));
        float s = (ws[j] > 0.0f) ? 1.0f : ((ws[j] < 0.0f) ? -1.0f : 0.0f);
        wb[j] = __float2bfloat16(s);
    }
    size_t base = (size_t)i * 4;
    *reinterpret_cast<uint2*>(g_xhi + base) = *reinterpret_cast<uint2*>(hi);
    *reinterpret_cast<uint2*>(g_xlo + base) = *reinterpret_cast<uint2*>(lo);
    *reinterpret_cast<uint2*>(g_wb  + base) = *reinterpret_cast<uint2*>(wb);
}

// ---------------------------------------------------------------------------
// PTX helpers
// ---------------------------------------------------------------------------
__device__ __forceinline__ void cp16(void* smem_ptr, const void* gmem_ptr) {
    uint32_t s = (uint32_t)__cvta_generic_to_shared(smem_ptr);
    asm volatile("cp.async.cg.shared.global [%0], [%1], 16;\n"
                 :: "r"(s), "l"(gmem_ptr) : "memory");
}

__device__ __forceinline__ void ldsm_x4(uint32_t* r, const void* p) {
    uint32_t a = (uint32_t)__cvta_generic_to_shared(p);
    asm volatile("ldmatrix.sync.aligned.m8n8.x4.shared.b16 {%0,%1,%2,%3}, [%4];\n"
                 : "=r"(r[0]), "=r"(r[1]), "=r"(r[2]), "=r"(r[3]) : "r"(a));
}

__device__ __forceinline__ void ldsm_x2(uint32_t* r, const void* p) {
    uint32_t a = (uint32_t)__cvta_generic_to_shared(p);
    asm volatile("ldmatrix.sync.aligned.m8n8.x2.shared.b16 {%0,%1}, [%2];\n"
                 : "=r"(r[0]), "=r"(r[1]) : "r"(a));
}

__device__ __forceinline__ void mma16816(float* d, const uint32_t* a, const uint32_t* b) {
    asm volatile("mma.sync.aligned.m16n8k16.row.col.f32.bf16.bf16.f32 "
                 "{%0,%1,%2,%3},{%4,%5,%6,%7},{%8,%9},{%0,%1,%2,%3};\n"
                 : "+f"(d[0]), "+f"(d[1]), "+f"(d[2]), "+f"(d[3])
                 : "r"(a[0]), "r"(a[1]), "r"(a[2]), "r"(a[3]),
                   "r"(b[0]), "r"(b[1]));
}

// ---------------------------------------------------------------------------
// GEMM: out[128x128 tile] = x_hi@Wb^T + x_lo@Wb^T + b
// 256 threads = 8 warps, 2(M) x 4(N) warp grid, warp tile 64x32.
// ---------------------------------------------------------------------------
__global__ void __launch_bounds__(256, 1)
gemm_kernel(const float* __restrict__ bias, float* __restrict__ out) {
    extern __shared__ __nv_bfloat16 smem[];
    const int tid   = threadIdx.x;
    const int lane  = tid & 31;
    const int warp  = tid >> 5;
    const int warpM = warp & 1;   // 0..1
    const int warpN = warp >> 1;  // 0..3
    const int mBase = blockIdx.y * MTILE;
    const int nBase = blockIdx.x * NTILE;

    float acc[4][4][4];
#pragma unroll
    for (int a = 0; a < 4; a++)
#pragma unroll
        for (int b = 0; b < 4; b++)
#pragma unroll
            for (int c = 0; c < 4; c++) acc[a][b][c] = 0.0f;

    // ---- prefetch one k-tile into buffer `buf` ----
    auto prefetch = [&](int kt, int buf) {
        const int k0 = kt * KTILE;
        __nv_bfloat16* s = smem + buf * STAGE_ELEMS;
#pragma unroll
        for (int c = tid; c < 512; c += 256) {   // 128 rows x 4 16B-chunks
            int row = c >> 2;
            int col = (c & 3) * 8;               // bf16 elements
            int so  = row * S_STRIDE + col;
            size_t goA = (size_t)(mBase + row) * N_DIM + k0 + col;
            size_t goB = (size_t)(nBase + row) * N_DIM + k0 + col;
            cp16(s + so,                  g_xhi + goA);
            cp16(s + TILE_ELEMS + so,     g_xlo + goA);
            cp16(s + 2 * TILE_ELEMS + so, g_wb  + goB);
        }
        asm volatile("cp.async.commit_group;\n" ::: "memory");
    };

    // ---- compute on buffer `buf` ----
    auto compute = [&](int buf) {
        __nv_bfloat16* sA = smem + buf * STAGE_ELEMS;
        __nv_bfloat16* sL = sA + TILE_ELEMS;
        __nv_bfloat16* sB = sA + 2 * TILE_ELEMS;
#pragma unroll
        for (int ks = 0; ks < 2; ks++) {
            const int k16 = ks * 16;
            uint32_t bf[4][2];
#pragma unroll
            for (int tn = 0; tn < 4; tn++) {
                int r = warpN * 32 + tn * 8 + (lane & 7);
                int c = k16 + ((lane >> 3) & 1) * 8;
                ldsm_x2(bf[tn], sB + r * S_STRIDE + c);
            }
            uint32_t ah[4][4], al[4][4];
#pragma unroll
            for (int tm = 0; tm < 4; tm++) {
                int r = warpM * 64 + tm * 16 + (lane & 7) + ((lane >> 3) & 1) * 8;
                int c = k16 + ((lane >> 4) & 1) * 8;
                ldsm_x4(ah[tm], sA + r * S_STRIDE + c);
                ldsm_x4(al[tm], sL + r * S_STRIDE + c);
            }
#pragma unroll
            for (int tm = 0; tm < 4; tm++)
#pragma unroll
                for (int tn = 0; tn < 4; tn++) {
                    mma16816(acc[tm][tn], ah[tm], bf[tn]);
                    mma16816(acc[tm][tn], al[tm], bf[tn]);
                }
        }
    };

    // ---- mainloop: double-buffered cp.async pipeline ----
    prefetch(0, 0);
    int buf = 0;
    for (int kt = 0; kt < NKT; kt++) {
        if (kt + 1 < NKT) {
            prefetch(kt + 1, buf ^ 1);
            asm volatile("cp.async.wait_group 1;\n" ::: "memory");
        } else {
            asm volatile("cp.async.wait_group 0;\n" ::: "memory");
        }
        __syncthreads();
        compute(buf);
        __syncthreads();
        buf ^= 1;
    }

    // ---- epilogue: + bias, fp32 store ----
    const int g  = lane >> 2;
    const int t4 = lane & 3;
    float2 bias2[4];
    int cols[4];
#pragma unroll
    for (int tn = 0; tn < 4; tn++) {
        cols[tn]  = nBase + warpN * 32 + tn * 8 + 2 * t4;
        bias2[tn] = *reinterpret_cast<const float2*>(bias + cols[tn]);
    }
#pragma unroll
    for (int tm = 0; tm < 4; tm++) {
        int r0 = mBase + warpM * 64 + tm * 16 + g;
#pragma unroll
        for (int tn = 0; tn < 4; tn++) {
            float2 v0, v1;
            v0.x = acc[tm][tn][0] + bias2[tn].x;
            v0.y = acc[tm][tn][1] + bias2[tn].y;
            v1.x = acc[tm][tn][2] + bias2[tn].x;
            v1.y = acc[tm][tn][3] + bias2[tn].y;
            *reinterpret_cast<float2*>(out + (size_t)r0 * N_DIM + cols[tn])       = v0;
            *reinterpret_cast<float2*>(out + (size_t)(r0 + 8) * N_DIM + cols[tn]) = v1;
        }
    }
}

// ---------------------------------------------------------------------------
extern "C" void kernel_launch(void* const* d_in, const int* in_sizes, int n_in,
                              void* d_out, int out_size) {
    const float* x = (const float*)d_in[0];
    const float* W = (const float*)d_in[1];
    const float* b = (const float*)d_in[2];
    float* out = (float*)d_out;

    const int n4 = (N_DIM * N_DIM) / 4;
    prep_kernel<<<(n4 + 255) / 256, 256>>>((const float4*)x, (const float4*)W, n4);

    cudaFuncSetAttribute(gemm_kernel, cudaFuncAttributeMaxDynamicSharedMemorySize,
                         SMEM_BYTES);
    dim3 grid(N_DIM / NTILE, N_DIM / MTILE);  // (32, 32)
    gemm_kernel<<<grid, 256, SMEM_BYTES>>>(b, out);
}

// round 3
// speedup vs baseline: 1.9379x; 1.9379x over previous
#include <cuda_runtime.h>
#include <cuda_fp16.h>
#include <cstdint>

// out[n,o] = sum_i x[n,i] * sign(W[o,i]) + b[o],  N=IN=OUT=4096, fp32 in/out.
//
// tcgen05 is unavailable (harness PTX target is compute_103, not 103a), so this
// targets the legacy HMMA pipe. Single fp16 GEMM: sign(W) is exact in fp16 and
// fp16(x) carries 11 mantissa bits -> norm rel err ~3e-4 << 1e-3. fp32 accum.
// 128x128x32 CTA tile, 8 warps (64x32 warp tiles), 4-stage cp.async pipeline,
// one __syncthreads per k-tile, 2 CTAs/SM via __launch_bounds__(256,2).

#define N_DIM 4096
constexpr int MTILE = 128;
constexpr int NTILE = 128;
constexpr int KTILE = 32;
constexpr int NKT = N_DIM / KTILE;            // 128
constexpr int S_STRIDE = 40;                  // fp16 elems; 80B rows: conflict-free ldmatrix
constexpr int TILE_ELEMS = 128 * S_STRIDE;    // 5120 fp16
constexpr int STAGE_ELEMS = 2 * TILE_ELEMS;   // A + B
constexpr int NSTAGE = 4;
constexpr int SMEM_BYTES = NSTAGE * STAGE_ELEMS * (int)sizeof(__half);  // 81920

__device__ __half g_xh[(size_t)N_DIM * N_DIM];
__device__ __half g_wb[(size_t)N_DIM * N_DIM];

// ---------------------------------------------------------------------------
// prep: binarize W -> fp16, cast x -> fp16
// ---------------------------------------------------------------------------
__global__ void prep_kernel(const float4* __restrict__ x,
                            const float4* __restrict__ W, int n4) {
    int i = blockIdx.x * blockDim.x + threadIdx.x;
    if (i >= n4) return;
    float4 xv = x[i];
    float4 wv = W[i];
    float xs[4] = {xv.x, xv.y, xv.z, xv.w};
    float ws[4] = {wv.x, wv.y, wv.z, wv.w};
    alignas(8) __half xh[4], wb[4];
#pragma unroll
    for (int j = 0; j < 4; j++) {
        xh[j] = __float2half_rn(xs[j]);
        float s = (ws[j] > 0.0f) ? 1.0f : ((ws[j] < 0.0f) ? -1.0f : 0.0f);
        wb[j] = __float2half_rn(s);
    }
    size_t base = (size_t)i * 4;
    *reinterpret_cast<uint2*>(g_xh + base) = *reinterpret_cast<uint2*>(xh);
    *reinterpret_cast<uint2*>(g_wb + base) = *reinterpret_cast<uint2*>(wb);
}

// ---------------------------------------------------------------------------
// PTX helpers
// ---------------------------------------------------------------------------
__device__ __forceinline__ void cp16(uint32_t smem_addr, const void* gmem_ptr) {
    asm volatile("cp.async.cg.shared.global [%0], [%1], 16;\n"
                 :: "r"(smem_addr), "l"(gmem_ptr) : "memory");
}

__device__ __forceinline__ void ldsm_x4(uint32_t* r, uint32_t a) {
    asm volatile("ldmatrix.sync.aligned.m8n8.x4.shared.b16 {%0,%1,%2,%3}, [%4];\n"
                 : "=r"(r[0]), "=r"(r[1]), "=r"(r[2]), "=r"(r[3]) : "r"(a));
}

__device__ __forceinline__ void ldsm_x2(uint32_t* r, uint32_t a) {
    asm volatile("ldmatrix.sync.aligned.m8n8.x2.shared.b16 {%0,%1}, [%2];\n"
                 : "=r"(r[0]), "=r"(r[1]) : "r"(a));
}

__device__ __forceinline__ void mma16816(float* d, const uint32_t* a, const uint32_t* b) {
    asm volatile("mma.sync.aligned.m16n8k16.row.col.f32.f16.f16.f32 "
                 "{%0,%1,%2,%3},{%4,%5,%6,%7},{%8,%9},{%0,%1,%2,%3};\n"
                 : "+f"(d[0]), "+f"(d[1]), "+f"(d[2]), "+f"(d[3])
                 : "r"(a[0]), "r"(a[1]), "r"(a[2]), "r"(a[3]),
                   "r"(b[0]), "r"(b[1]));
}

// ---------------------------------------------------------------------------
// GEMM: 256 threads = 8 warps, 2(M) x 4(N) warp grid, warp tile 64x32.
// ---------------------------------------------------------------------------
__global__ void __launch_bounds__(256, 2)
gemm_kernel(const float* __restrict__ bias, float* __restrict__ out) {
    extern __shared__ __half smem[];
    const uint32_t smem_base = (uint32_t)__cvta_generic_to_shared(smem);
    const int tid   = threadIdx.x;
    const int lane  = tid & 31;
    const int warp  = tid >> 5;
    const int warpM = warp & 1;
    const int warpN = warp >> 1;
    const int mBase = blockIdx.y * MTILE;
    const int nBase = blockIdx.x * NTILE;

    float acc[4][4][4];
#pragma unroll
    for (int a = 0; a < 4; a++)
#pragma unroll
        for (int b = 0; b < 4; b++)
#pragma unroll
            for (int c = 0; c < 4; c++) acc[a][b][c] = 0.0f;

    // per-thread cp.async assignment: 2 chunks each of A and B per k-tile
    // chunk id = tid + it*256; row = id/4 (4x16B chunks per 32-elem row)
    const int r0 = tid >> 2;                 // rows 0..63   (it=0)
    const int r1 = (tid + 256) >> 2;         // rows 64..127 (it=1)
    const int c0 = (tid & 3) * 8;            // fp16 col offset within k-tile
    const __half* gA0 = g_xh + (size_t)(mBase + r0) * N_DIM + c0;
    const __half* gA1 = g_xh + (size_t)(mBase + r1) * N_DIM + c0;
    const __half* gB0 = g_wb + (size_t)(nBase + r0) * N_DIM + c0;
    const __half* gB1 = g_wb + (size_t)(nBase + r1) * N_DIM + c0;
    const uint32_t soA0 = (r0 * S_STRIDE + c0) * 2;
    const uint32_t soA1 = (r1 * S_STRIDE + c0) * 2;
    const uint32_t soB0 = soA0 + TILE_ELEMS * 2;
    const uint32_t soB1 = soA1 + TILE_ELEMS * 2;

    auto prefetch = [&](int kt) {
        const uint32_t sb = smem_base + (kt & 3) * (STAGE_ELEMS * 2);
        const int k0 = kt * KTILE;
        cp16(sb + soA0, gA0 + k0);
        cp16(sb + soA1, gA1 + k0);
        cp16(sb + soB0, gB0 + k0);
        cp16(sb + soB1, gB1 + k0);
        asm volatile("cp.async.commit_group;\n" ::: "memory");
    };

    // per-warp ldmatrix smem addresses (byte offsets within a stage)
    const uint32_t aRow = warpM * 64 + (lane & 15);
    const uint32_t aCol = ((lane >> 4) & 1) * 8;
    const uint32_t aAddr0 = smem_base + (aRow * S_STRIDE + aCol) * 2;
    const uint32_t bRow = warpN * 32 + (lane & 7);
    const uint32_t bCol = ((lane >> 3) & 1) * 8;
    const uint32_t bAddr0 = smem_base + (TILE_ELEMS + bRow * S_STRIDE + bCol) * 2;

    auto compute = [&](int s) {
        const uint32_t stOff = (uint32_t)s * (STAGE_ELEMS * 2);
#pragma unroll
        for (int ks = 0; ks < 2; ks++) {
            const uint32_t kOff = ks * 16 * 2;
            uint32_t bf[4][2];
#pragma unroll
            for (int tn = 0; tn < 4; tn++)
                ldsm_x2(bf[tn], bAddr0 + stOff + kOff + tn * (8 * S_STRIDE * 2));
            uint32_t ah[4][4];
#pragma unroll
            for (int tm = 0; tm < 4; tm++)
                ldsm_x4(ah[tm], aAddr0 + stOff + kOff + tm * (16 * S_STRIDE * 2));
#pragma unroll
            for (int tm = 0; tm < 4; tm++)
#pragma unroll
                for (int tn = 0; tn < 4; tn++)
                    mma16816(acc[tm][tn], ah[tm], bf[tn]);
        }
    };

    prefetch(0);
    prefetch(1);
    prefetch(2);

    for (int kt = 0; kt < NKT; kt++) {
        if (kt <= NKT - 3)
            asm volatile("cp.async.wait_group 2;\n" ::: "memory");
        else if (kt == NKT - 2)
            asm volatile("cp.async.wait_group 1;\n" ::: "memory");
        else
            asm volatile("cp.async.wait_group 0;\n" ::: "memory");
        __syncthreads();
        if (kt + 3 < NKT) prefetch(kt + 3);
        compute(kt & 3);
    }

    // epilogue: + bias, fp32 store
    const int g  = lane >> 2;
    const int t4 = lane & 3;
    float2 bias2[4];
    int cols[4];
#pragma unroll
    for (int tn = 0; tn < 4; tn++) {
        cols[tn]  = nBase + warpN * 32 + tn * 8 + 2 * t4;
        bias2[tn] = *reinterpret_cast<const float2*>(bias + cols[tn]);
    }
#pragma unroll
    for (int tm = 0; tm < 4; tm++) {
        int rr = mBase + warpM * 64 + tm * 16 + g;
#pragma unroll
        for (int tn = 0; tn < 4; tn++) {
            float2 v0, v1;
            v0.x = acc[tm][tn][0] + bias2[tn].x;
            v0.y = acc[tm][tn][1] + bias2[tn].y;
            v1.x = acc[tm][tn][2] + bias2[tn].x;
            v1.y = acc[tm][tn][3] + bias2[tn].y;
            *reinterpret_cast<float2*>(out + (size_t)rr * N_DIM + cols[tn])       = v0;
            *reinterpret_cast<float2*>(out + (size_t)(rr + 8) * N_DIM + cols[tn]) = v1;
        }
    }
}

// ---------------------------------------------------------------------------
extern "C" void kernel_launch(void* const* d_in, const int* in_sizes, int n_in,
                              void* d_out, int out_size) {
    const float* x = (const float*)d_in[0];
    const float* W = (const float*)d_in[1];
    const float* b = (const float*)d_in[2];
    float* out = (float*)d_out;

    const int n4 = (N_DIM * N_DIM) / 4;
    prep_kernel<<<(n4 + 255) / 256, 256>>>((const float4*)x, (const float4*)W, n4);

    cudaFuncSetAttribute(gemm_kernel, cudaFuncAttributeMaxDynamicSharedMemorySize,
                         SMEM_BYTES);
    dim3 grid(N_DIM / NTILE, N_DIM / MTILE);  // (32, 32)
    gemm_kernel<<<grid, 256, SMEM_BYTES>>>(b, out);
}